// round 1
// baseline (speedup 1.0000x reference)
#include <cuda_runtime.h>
#include <cuda_bf16.h>
#include <math_constants.h>

// Problem constants
#define BATCH 2
#define SEQ   2048
#define EMB   1024
#define HEADS 16
#define HS    64
#define MROWS (BATCH * SEQ)      // 4096
#define QKVC  (3 * EMB)          // 3072

// Scratch (allocation-free rule: __device__ globals)
__device__ float g_qkv[MROWS * QKVC];     // [B*T, 3C]
__device__ float g_attn[MROWS * EMB];     // [B*T, C] pre-proj attention output

// ---------------------------------------------------------------------------
// Generic 64x64-tile fp32 GEMM: C[M,N] = A[M,K] @ B[K,N] (+ bias)
// 256 threads, 4x4 microtile per thread, K-step 16.
// ---------------------------------------------------------------------------
template <bool HAS_BIAS>
__global__ __launch_bounds__(256) void gemm64(
    const float* __restrict__ A, const float* __restrict__ B,
    const float* __restrict__ bias, float* __restrict__ C,
    int M, int N, int K)
{
    __shared__ float As[16][68];   // [kk][row]
    __shared__ float Bs[16][68];   // [kk][col]

    const int tid = threadIdx.x;
    const int tx = tid & 15;
    const int ty = tid >> 4;
    const int m0 = blockIdx.y * 64;
    const int n0 = blockIdx.x * 64;

    float acc[4][4] = {};

    for (int k0 = 0; k0 < K; k0 += 16) {
        // Load A tile 64x16 (transposed into As[kk][row])
        {
            int r  = tid >> 2;          // 0..63
            int ks = (tid & 3) * 4;     // 0,4,8,12
            float4 a = *(const float4*)&A[(size_t)(m0 + r) * K + k0 + ks];
            As[ks + 0][r] = a.x;
            As[ks + 1][r] = a.y;
            As[ks + 2][r] = a.z;
            As[ks + 3][r] = a.w;
        }
        // Load B tile 16x64
        {
            int kk = tid >> 4;          // 0..15
            int cs = (tid & 15) * 4;    // 0..60
            float4 b = *(const float4*)&B[(size_t)(k0 + kk) * N + n0 + cs];
            *(float4*)&Bs[kk][cs] = b;
        }
        __syncthreads();

        #pragma unroll
        for (int kk = 0; kk < 16; kk++) {
            float4 a4 = *(const float4*)&As[kk][ty * 4];
            float4 b4 = *(const float4*)&Bs[kk][tx * 4];
            const float av[4] = {a4.x, a4.y, a4.z, a4.w};
            const float bv[4] = {b4.x, b4.y, b4.z, b4.w};
            #pragma unroll
            for (int a = 0; a < 4; a++)
                #pragma unroll
                for (int b = 0; b < 4; b++)
                    acc[a][b] = fmaf(av[a], bv[b], acc[a][b]);
        }
        __syncthreads();
    }

    // Epilogue
    #pragma unroll
    for (int a = 0; a < 4; a++) {
        int row = m0 + ty * 4 + a;
        int col = n0 + tx * 4;
        float4 r;
        r.x = acc[a][0]; r.y = acc[a][1]; r.z = acc[a][2]; r.w = acc[a][3];
        if (HAS_BIAS) {
            float4 bb = *(const float4*)&bias[col];
            r.x += bb.x; r.y += bb.y; r.z += bb.z; r.w += bb.w;
        }
        *(float4*)&C[(size_t)row * N + col] = r;
    }
}

// ---------------------------------------------------------------------------
// Flash-attention style kernel.
// Block: 64 query rows of one (b,h). 256 threads (16x16), 4x4 microtile.
// Streams K/V in 64-key tiles with online softmax. Causal: only iterate key
// tiles with j0 <= q0; the diagonal tile applies the mask.
// Output written directly in [B, T, H*HS] layout.
// ---------------------------------------------------------------------------
#define PAD 68
#define ATTN_SMEM ((4 * 64 * PAD + 3 * 64) * sizeof(float))

__global__ __launch_bounds__(256) void attn_kernel(
    const float* __restrict__ qkv, float* __restrict__ out)
{
    extern __shared__ float sm[];
    float* Qs  = sm;                    // [d][row]   64xPAD
    float* Ks  = Qs + 64 * PAD;         // [d][key]   64xPAD
    float* Vs  = Ks + 64 * PAD;         // [key][d]   64xPAD
    float* Ss  = Vs + 64 * PAD;         // [row][key] 64xPAD
    float* sc_s = Ss + 64 * PAD;        // 64  (rescale factor)
    float* l_s  = sc_s + 64;            // 64  (final 1/l)
    // one extra 64-float slot unused (kept for alignment)

    const int tid = threadIdx.x;
    const int tx = tid & 15;
    const int ty = tid >> 4;
    const int q0 = blockIdx.x * 64;
    const int bh = blockIdx.y;
    const int b = bh >> 4;
    const int h = bh & 15;

    const size_t rstride = QKVC;  // 3072 floats per token row
    const float* qbase = qkv + (size_t)b * SEQ * rstride + h * HS;
    const float* kbase = qbase + EMB;
    const float* vbase = qbase + 2 * EMB;

    // Load Q tile (64 rows x 64 d) transposed: Qs[d][row]
    #pragma unroll
    for (int i = 0; i < 4; i++) {
        int idx = tid + i * 256;          // float4 index 0..1023
        int row = idx >> 4;
        int ds  = (idx & 15) * 4;
        float4 q = *(const float4*)&qbase[(size_t)(q0 + row) * rstride + ds];
        Qs[(ds + 0) * PAD + row] = q.x;
        Qs[(ds + 1) * PAD + row] = q.y;
        Qs[(ds + 2) * PAD + row] = q.z;
        Qs[(ds + 3) * PAD + row] = q.w;
    }

    float o[4][4] = {};
    float m_run = -CUDART_INF_F;   // valid only for tid < 64
    float l_run = 0.0f;

    __syncthreads();

    for (int j0 = 0; j0 <= q0; j0 += 64) {
        // Load K tile transposed Ks[d][key], V tile natural Vs[key][d]
        #pragma unroll
        for (int i = 0; i < 4; i++) {
            int idx = tid + i * 256;
            int row = idx >> 4;
            int ds  = (idx & 15) * 4;
            float4 k = *(const float4*)&kbase[(size_t)(j0 + row) * rstride + ds];
            Ks[(ds + 0) * PAD + row] = k.x;
            Ks[(ds + 1) * PAD + row] = k.y;
            Ks[(ds + 2) * PAD + row] = k.z;
            Ks[(ds + 3) * PAD + row] = k.w;
            float4 v = *(const float4*)&vbase[(size_t)(j0 + row) * rstride + ds];
            *(float4*)&Vs[row * PAD + ds] = v;
        }
        __syncthreads();

        // S = Q @ K^T * scale  (4x4 per thread)
        float s[4][4] = {};
        #pragma unroll 8
        for (int d = 0; d < 64; d++) {
            float4 q4 = *(const float4*)&Qs[d * PAD + ty * 4];
            float4 k4 = *(const float4*)&Ks[d * PAD + tx * 4];
            const float qv[4] = {q4.x, q4.y, q4.z, q4.w};
            const float kv[4] = {k4.x, k4.y, k4.z, k4.w};
            #pragma unroll
            for (int a = 0; a < 4; a++)
                #pragma unroll
                for (int bb = 0; bb < 4; bb++)
                    s[a][bb] = fmaf(qv[a], kv[bb], s[a][bb]);
        }
        const float scale = 0.125f;  // 1/sqrt(64)
        if (j0 == q0) {
            // diagonal tile: mask kj > qi
            #pragma unroll
            for (int a = 0; a < 4; a++) {
                int qi = ty * 4 + a;
                #pragma unroll
                for (int bb = 0; bb < 4; bb++) {
                    int kj = tx * 4 + bb;
                    s[a][bb] = (kj > qi) ? -CUDART_INF_F : s[a][bb] * scale;
                }
            }
        } else {
            #pragma unroll
            for (int a = 0; a < 4; a++)
                #pragma unroll
                for (int bb = 0; bb < 4; bb++)
                    s[a][bb] *= scale;
        }
        // Write S to smem
        #pragma unroll
        for (int a = 0; a < 4; a++) {
            float4 r;
            r.x = s[a][0]; r.y = s[a][1]; r.z = s[a][2]; r.w = s[a][3];
            *(float4*)&Ss[(ty * 4 + a) * PAD + tx * 4] = r;
        }
        __syncthreads();

        // Online softmax update: one thread per row (tid < 64)
        if (tid < 64) {
            float* srow = &Ss[tid * PAD];
            float mx = m_run;
            #pragma unroll 8
            for (int j = 0; j < 64; j++) mx = fmaxf(mx, srow[j]);
            float rescale = __expf(m_run - mx);   // 0 on first tile (m_run=-inf)
            float sum = 0.0f;
            #pragma unroll 8
            for (int j = 0; j < 64; j++) {
                float p = __expf(srow[j] - mx);
                srow[j] = p;
                sum += p;
            }
            l_run = l_run * rescale + sum;
            m_run = mx;
            sc_s[tid] = rescale;
        }
        __syncthreads();

        // Rescale O and accumulate P @ V
        float sca[4];
        #pragma unroll
        for (int a = 0; a < 4; a++) sca[a] = sc_s[ty * 4 + a];
        #pragma unroll
        for (int a = 0; a < 4; a++)
            #pragma unroll
            for (int bb = 0; bb < 4; bb++)
                o[a][bb] *= sca[a];

        #pragma unroll 8
        for (int kk = 0; kk < 64; kk++) {
            float4 v4 = *(const float4*)&Vs[kk * PAD + tx * 4];
            const float vv[4] = {v4.x, v4.y, v4.z, v4.w};
            #pragma unroll
            for (int a = 0; a < 4; a++) {
                float p = Ss[(ty * 4 + a) * PAD + kk];  // broadcast across tx
                #pragma unroll
                for (int bb = 0; bb < 4; bb++)
                    o[a][bb] = fmaf(p, vv[bb], o[a][bb]);
            }
        }
        __syncthreads();  // before next tile overwrites Ks/Vs/Ss
    }

    if (tid < 64) l_s[tid] = 1.0f / l_run;
    __syncthreads();

    // Write O to out[b, q0+row, h*HS + col]
    #pragma unroll
    for (int a = 0; a < 4; a++) {
        int row = ty * 4 + a;
        float inv = l_s[row];
        float4 r;
        r.x = o[a][0] * inv; r.y = o[a][1] * inv;
        r.z = o[a][2] * inv; r.w = o[a][3] * inv;
        size_t off = (size_t)(b * SEQ + q0 + row) * EMB + h * HS + tx * 4;
        *(float4*)&out[off] = r;
    }
}

// ---------------------------------------------------------------------------
// Launch
// ---------------------------------------------------------------------------
extern "C" void kernel_launch(void* const* d_in, const int* in_sizes, int n_in,
                              void* d_out, int out_size)
{
    const float* x      = (const float*)d_in[0];  // [B,T,EMB]
    const float* w_qkv  = (const float*)d_in[1];  // [EMB, 3*EMB]
    const float* w_proj = (const float*)d_in[2];  // [EMB, EMB]
    const float* b_proj = (const float*)d_in[3];  // [EMB]
    float* out = (float*)d_out;

    float *qkvp = nullptr, *attnp = nullptr;
    cudaGetSymbolAddress((void**)&qkvp, g_qkv);
    cudaGetSymbolAddress((void**)&attnp, g_attn);

    // 1) QKV projection: [4096,1024] @ [1024,3072]
    {
        dim3 grid(QKVC / 64, MROWS / 64);
        gemm64<false><<<grid, 256>>>(x, w_qkv, nullptr, qkvp, MROWS, QKVC, EMB);
    }

    // 2) Causal multi-head attention
    {
        cudaFuncSetAttribute(attn_kernel,
                             cudaFuncAttributeMaxDynamicSharedMemorySize,
                             (int)ATTN_SMEM);
        dim3 grid(SEQ / 64, BATCH * HEADS);
        attn_kernel<<<grid, 256, ATTN_SMEM>>>(qkvp, attnp);
    }

    // 3) Output projection + bias: [4096,1024] @ [1024,1024] + b
    {
        dim3 grid(EMB / 64, MROWS / 64);
        gemm64<true><<<grid, 256>>>(attnp, w_proj, b_proj, out, MROWS, EMB, EMB);
    }
}

// round 8
// speedup vs baseline: 3.2005x; 3.2005x over previous
#include <cuda_runtime.h>
#include <cuda_fp16.h>
#include <math_constants.h>
#include <cstdint>
#include <cstddef>

typedef unsigned int u32;

// ---------------------------------------------------------------------------
// Problem constants
// ---------------------------------------------------------------------------
constexpr int kBatch = 2;
constexpr int kSeq   = 2048;
constexpr int kEmb   = 1024;
constexpr int kHs    = 64;
constexpr int kRows  = kBatch * kSeq;   // 4096
constexpr int kQkvC  = 3 * kEmb;        // 3072

// Scratch (allocation-free rule: __device__ globals; zero-initialized)
__device__ float  g_qkv[kRows * kQkvC];
__device__ float  g_attn[kRows * kEmb];
__device__ __half g_x16[kRows * kEmb];
__device__ __half g_wqkv16[kEmb * kQkvC];
__device__ __half g_wproj16[kEmb * kEmb];
__device__ __half g_attn16[kRows * kEmb];
__device__ float  g_zero_bias[kQkvC];   // stays all-zero

// ---------------------------------------------------------------------------
// PTX helpers
// ---------------------------------------------------------------------------
static __device__ __forceinline__ void ldsm_x4(u32* r, u32 addr) {
    asm volatile(
        "ldmatrix.sync.aligned.m8n8.x4.shared.b16 { %0, %1, %2, %3 }, [ %4 ];\n"
        : "=r"(r[0]), "=r"(r[1]), "=r"(r[2]), "=r"(r[3])
        : "r"(addr));
}

static __device__ __forceinline__ void ldsm_x4_t(u32* r, u32 addr) {
    asm volatile(
        "ldmatrix.sync.aligned.m8n8.x4.trans.shared.b16 { %0, %1, %2, %3 }, [ %4 ];\n"
        : "=r"(r[0]), "=r"(r[1]), "=r"(r[2]), "=r"(r[3])
        : "r"(addr));
}

static __device__ __forceinline__ void hmma(float* acc, const u32* af, const u32* bf) {
    asm volatile(
        "mma.sync.aligned.m16n8k16.row.col.f32.f16.f16.f32 "
        "{ %0, %1, %2, %3 }, { %4, %5, %6, %7 }, { %8, %9 }, { %0, %1, %2, %3 };\n"
        : "+f"(acc[0]), "+f"(acc[1]), "+f"(acc[2]), "+f"(acc[3])
        : "r"(af[0]), "r"(af[1]), "r"(af[2]), "r"(af[3]),
          "r"(bf[0]), "r"(bf[1]));
}

// ---------------------------------------------------------------------------
// fp32 -> fp16 conversion, 8 elems/thread
// ---------------------------------------------------------------------------
__global__ __launch_bounds__(256) void f2h_kernel(
    const float* __restrict__ src, __half* __restrict__ dst, int n)
{
    int i = (blockIdx.x * 256 + threadIdx.x) * 8;
    if (i >= n) return;
    float4 v0 = *(const float4*)(src + i);
    float4 v1 = *(const float4*)(src + i + 4);
    __half2 h[4];
    h[0] = __floats2half2_rn(v0.x, v0.y);
    h[1] = __floats2half2_rn(v0.z, v0.w);
    h[2] = __floats2half2_rn(v1.x, v1.y);
    h[3] = __floats2half2_rn(v1.z, v1.w);
    *(uint4*)(dst + i) = *(uint4*)h;
}

// ---------------------------------------------------------------------------
// Tensor-core GEMM: C[M,N] = A[M,K](fp16) @ B[K,N](fp16) + bias, fp32 accum.
// CTA tile 128x128, 8 warps (warp tile 32x64), K-step 32, double-buffered.
// ---------------------------------------------------------------------------
constexpr int kAStr = 56;    // A smem row stride (halves): 128x32 tile
constexpr int kBStr = 136;   // B smem row stride (halves): 32x128 tile

__global__ __launch_bounds__(256) void gemm_mma_kernel(
    const __half* __restrict__ Ap, const __half* __restrict__ Bp,
    const float* __restrict__ bias, float* __restrict__ Cp,
    int M, int N, int K)
{
    __shared__ __half As[2][128 * kAStr];
    __shared__ __half Bs[2][32 * kBStr];

    const int tid  = threadIdx.x;
    const int lane = tid & 31;
    const int wid  = tid >> 5;
    const int warp_m = wid & 3;
    const int warp_n = wid >> 2;
    const int m0 = blockIdx.y * 128;
    const int n0 = blockIdx.x * 128;

    const int a_r0 = tid >> 2;
    const int a_c  = (tid & 3) * 8;
    const int b_r0 = tid >> 4;
    const int b_c  = (tid & 15) * 8;

    float acc[2][8][4];
    for (int mt = 0; mt < 2; mt++) {
        for (int nt = 0; nt < 8; nt++) {
            acc[mt][nt][0] = 0.0f;
            acc[mt][nt][1] = 0.0f;
            acc[mt][nt][2] = 0.0f;
            acc[mt][nt][3] = 0.0f;
        }
    }

    uint4 ra0;
    uint4 ra1;
    uint4 rb0;
    uint4 rb1;

    // prologue: global load of K-tile 0
    ra0 = *(const uint4*)(Ap + (size_t)(m0 + a_r0) * K + a_c);
    ra1 = *(const uint4*)(Ap + (size_t)(m0 + a_r0 + 64) * K + a_c);
    rb0 = *(const uint4*)(Bp + (size_t)b_r0 * N + n0 + b_c);
    rb1 = *(const uint4*)(Bp + (size_t)(b_r0 + 16) * N + n0 + b_c);

    int buf = 0;
    *(uint4*)(&As[buf][a_r0 * kAStr + a_c]) = ra0;
    *(uint4*)(&As[buf][(a_r0 + 64) * kAStr + a_c]) = ra1;
    *(uint4*)(&Bs[buf][b_r0 * kBStr + b_c]) = rb0;
    *(uint4*)(&Bs[buf][(b_r0 + 16) * kBStr + b_c]) = rb1;
    __syncthreads();

    const int iters = K / 32;
    for (int it = 0; it < iters; it++) {
        if (it + 1 < iters) {
            int k0 = (it + 1) * 32;
            ra0 = *(const uint4*)(Ap + (size_t)(m0 + a_r0) * K + k0 + a_c);
            ra1 = *(const uint4*)(Ap + (size_t)(m0 + a_r0 + 64) * K + k0 + a_c);
            rb0 = *(const uint4*)(Bp + (size_t)(k0 + b_r0) * N + n0 + b_c);
            rb1 = *(const uint4*)(Bp + (size_t)(k0 + b_r0 + 16) * N + n0 + b_c);
        }

        u32 sA = (u32)__cvta_generic_to_shared(&As[buf][0]);
        u32 sB = (u32)__cvta_generic_to_shared(&Bs[buf][0]);
        #pragma unroll
        for (int ks = 0; ks < 2; ks++) {
            u32 afrag[2][4];
            #pragma unroll
            for (int mt = 0; mt < 2; mt++) {
                int arow = warp_m * 32 + mt * 16 + (lane & 15);
                int acol = ks * 16 + (lane >> 4) * 8;
                ldsm_x4(afrag[mt], sA + (u32)(arow * kAStr + acol) * 2u);
            }
            u32 bfrag[8][2];
            #pragma unroll
            for (int p = 0; p < 4; p++) {
                int krow = ks * 16 + (lane & 7) + ((lane >> 3) & 1) * 8;
                int ncol = warp_n * 64 + p * 16 + (lane >> 4) * 8;
                u32 rr[4];
                ldsm_x4_t(rr, sB + (u32)(krow * kBStr + ncol) * 2u);
                bfrag[2 * p][0] = rr[0];
                bfrag[2 * p][1] = rr[1];
                bfrag[2 * p + 1][0] = rr[2];
                bfrag[2 * p + 1][1] = rr[3];
            }
            #pragma unroll
            for (int mt = 0; mt < 2; mt++) {
                #pragma unroll
                for (int nt = 0; nt < 8; nt++) {
                    hmma(acc[mt][nt], afrag[mt], bfrag[nt]);
                }
            }
        }

        if (it + 1 < iters) {
            int nb = buf ^ 1;
            *(uint4*)(&As[nb][a_r0 * kAStr + a_c]) = ra0;
            *(uint4*)(&As[nb][(a_r0 + 64) * kAStr + a_c]) = ra1;
            *(uint4*)(&Bs[nb][b_r0 * kBStr + b_c]) = rb0;
            *(uint4*)(&Bs[nb][(b_r0 + 16) * kBStr + b_c]) = rb1;
            __syncthreads();
            buf = nb;
        }
    }

    // epilogue (+bias)
    #pragma unroll
    for (int mt = 0; mt < 2; mt++) {
        #pragma unroll
        for (int nt = 0; nt < 8; nt++) {
            int orow = m0 + warp_m * 32 + mt * 16 + (lane >> 2);
            int ocol = n0 + warp_n * 64 + nt * 8 + (lane & 3) * 2;
            float2 bb = *(const float2*)(bias + ocol);
            float2 v0;
            float2 v1;
            v0.x = acc[mt][nt][0] + bb.x;
            v0.y = acc[mt][nt][1] + bb.y;
            v1.x = acc[mt][nt][2] + bb.x;
            v1.y = acc[mt][nt][3] + bb.y;
            *(float2*)(Cp + (size_t)orow * N + ocol) = v0;
            *(float2*)(Cp + (size_t)(orow + 8) * N + ocol) = v1;
        }
    }
}

// ---------------------------------------------------------------------------
// Flash-attention style kernel (fp32; same structure as the R1 passing kernel)
// ---------------------------------------------------------------------------
constexpr int kPad = 68;
constexpr int kAttnSmemBytes = (4 * 64 * kPad + 3 * 64) * (int)sizeof(float);

__global__ __launch_bounds__(256) void attn_kernel(
    const float* __restrict__ qkv, float* __restrict__ outp)
{
    extern __shared__ float smf[];
    float* Qs = smf;
    float* Ks = Qs + 64 * kPad;
    float* Vs = Ks + 64 * kPad;
    float* Ss = Vs + 64 * kPad;
    float* sc_s = Ss + 64 * kPad;
    float* l_s = sc_s + 64;

    const int tid = threadIdx.x;
    const int tx = tid & 15;
    const int ty = tid >> 4;
    const int q0 = blockIdx.x * 64;
    const int bh = blockIdx.y;
    const int bi = bh >> 4;
    const int hi = bh & 15;

    const size_t rstride = (size_t)kQkvC;
    const float* qbase = qkv + (size_t)bi * kSeq * rstride + hi * kHs;
    const float* kbase = qbase + kEmb;
    const float* vbase = qbase + 2 * kEmb;

    #pragma unroll
    for (int i = 0; i < 4; i++) {
        int idx = tid + i * 256;
        int row = idx >> 4;
        int ds  = (idx & 15) * 4;
        float4 qv = *(const float4*)(qbase + (size_t)(q0 + row) * rstride + ds);
        Qs[(ds + 0) * kPad + row] = qv.x;
        Qs[(ds + 1) * kPad + row] = qv.y;
        Qs[(ds + 2) * kPad + row] = qv.z;
        Qs[(ds + 3) * kPad + row] = qv.w;
    }

    float o[4][4] = {};
    float m_run = -CUDART_INF_F;
    float l_run = 0.0f;

    __syncthreads();

    for (int j0 = 0; j0 <= q0; j0 += 64) {
        #pragma unroll
        for (int i = 0; i < 4; i++) {
            int idx = tid + i * 256;
            int row = idx >> 4;
            int ds  = (idx & 15) * 4;
            float4 kv = *(const float4*)(kbase + (size_t)(j0 + row) * rstride + ds);
            Ks[(ds + 0) * kPad + row] = kv.x;
            Ks[(ds + 1) * kPad + row] = kv.y;
            Ks[(ds + 2) * kPad + row] = kv.z;
            Ks[(ds + 3) * kPad + row] = kv.w;
            float4 vv = *(const float4*)(vbase + (size_t)(j0 + row) * rstride + ds);
            *(float4*)(&Vs[row * kPad + ds]) = vv;
        }
        __syncthreads();

        float s[4][4] = {};
        #pragma unroll 8
        for (int d = 0; d < 64; d++) {
            float4 q4 = *(const float4*)(&Qs[d * kPad + ty * 4]);
            float4 k4 = *(const float4*)(&Ks[d * kPad + tx * 4]);
            float qa[4];
            float ka[4];
            qa[0] = q4.x; qa[1] = q4.y; qa[2] = q4.z; qa[3] = q4.w;
            ka[0] = k4.x; ka[1] = k4.y; ka[2] = k4.z; ka[3] = k4.w;
            #pragma unroll
            for (int a = 0; a < 4; a++) {
                #pragma unroll
                for (int e = 0; e < 4; e++) {
                    s[a][e] = fmaf(qa[a], ka[e], s[a][e]);
                }
            }
        }
        const float scale = 0.125f;
        if (j0 == q0) {
            #pragma unroll
            for (int a = 0; a < 4; a++) {
                int qi = ty * 4 + a;
                #pragma unroll
                for (int e = 0; e < 4; e++) {
                    int kj = tx * 4 + e;
                    s[a][e] = (kj > qi) ? -CUDART_INF_F : s[a][e] * scale;
                }
            }
        } else {
            #pragma unroll
            for (int a = 0; a < 4; a++) {
                #pragma unroll
                for (int e = 0; e < 4; e++) {
                    s[a][e] *= scale;
                }
            }
        }
        #pragma unroll
        for (int a = 0; a < 4; a++) {
            float4 rv;
            rv.x = s[a][0]; rv.y = s[a][1]; rv.z = s[a][2]; rv.w = s[a][3];
            *(float4*)(&Ss[(ty * 4 + a) * kPad + tx * 4]) = rv;
        }
        __syncthreads();

        if (tid < 64) {
            float* srow = &Ss[tid * kPad];
            float mx = m_run;
            #pragma unroll 8
            for (int j = 0; j < 64; j++) mx = fmaxf(mx, srow[j]);
            float rescale = __expf(m_run - mx);
            float ssum = 0.0f;
            #pragma unroll 8
            for (int j = 0; j < 64; j++) {
                float p = __expf(srow[j] - mx);
                srow[j] = p;
                ssum += p;
            }
            l_run = l_run * rescale + ssum;
            m_run = mx;
            sc_s[tid] = rescale;
        }
        __syncthreads();

        float sca[4];
        #pragma unroll
        for (int a = 0; a < 4; a++) sca[a] = sc_s[ty * 4 + a];
        #pragma unroll
        for (int a = 0; a < 4; a++) {
            #pragma unroll
            for (int e = 0; e < 4; e++) {
                o[a][e] *= sca[a];
            }
        }

        #pragma unroll 8
        for (int kk = 0; kk < 64; kk++) {
            float4 v4 = *(const float4*)(&Vs[kk * kPad + tx * 4]);
            float va[4];
            va[0] = v4.x; va[1] = v4.y; va[2] = v4.z; va[3] = v4.w;
            #pragma unroll
            for (int a = 0; a < 4; a++) {
                float p = Ss[(ty * 4 + a) * kPad + kk];
                #pragma unroll
                for (int e = 0; e < 4; e++) {
                    o[a][e] = fmaf(p, va[e], o[a][e]);
                }
            }
        }
        __syncthreads();
    }

    if (tid < 64) l_s[tid] = 1.0f / l_run;
    __syncthreads();

    #pragma unroll
    for (int a = 0; a < 4; a++) {
        int row = ty * 4 + a;
        float inv = l_s[row];
        float4 rv;
        rv.x = o[a][0] * inv;
        rv.y = o[a][1] * inv;
        rv.z = o[a][2] * inv;
        rv.w = o[a][3] * inv;
        size_t off = (size_t)(bi * kSeq + q0 + row) * kEmb + hi * kHs + tx * 4;
        *(float4*)(outp + off) = rv;
    }
}

// ---------------------------------------------------------------------------
// Launch
// ---------------------------------------------------------------------------
extern "C" void kernel_launch(void* const* d_in, const int* in_sizes, int n_in,
                              void* d_out, int out_size)
{
    const float* x = (const float*)d_in[0];
    const float* w_qkv = (const float*)d_in[1];
    const float* w_proj = (const float*)d_in[2];
    const float* b_proj = (const float*)d_in[3];
    float* outp = (float*)d_out;

    float* qkvp = 0;
    float* attnp = 0;
    float* zbias = 0;
    __half* x16 = 0;
    __half* wq16 = 0;
    __half* wp16 = 0;
    __half* at16 = 0;
    cudaGetSymbolAddress((void**)&qkvp, g_qkv);
    cudaGetSymbolAddress((void**)&attnp, g_attn);
    cudaGetSymbolAddress((void**)&zbias, g_zero_bias);
    cudaGetSymbolAddress((void**)&x16, g_x16);
    cudaGetSymbolAddress((void**)&wq16, g_wqkv16);
    cudaGetSymbolAddress((void**)&wp16, g_wproj16);
    cudaGetSymbolAddress((void**)&at16, g_attn16);

    // fp32 -> fp16 conversions
    f2h_kernel<<<(kRows * kEmb) / 2048, 256>>>(x, x16, kRows * kEmb);
    f2h_kernel<<<(kEmb * kQkvC) / 2048, 256>>>(w_qkv, wq16, kEmb * kQkvC);
    f2h_kernel<<<(kEmb * kEmb) / 2048, 256>>>(w_proj, wp16, kEmb * kEmb);

    // 1) QKV projection (tensor cores), bias = zeros
    {
        dim3 grid1(kQkvC / 128, kRows / 128);
        gemm_mma_kernel<<<grid1, 256>>>(x16, wq16, zbias, qkvp, kRows, kQkvC, kEmb);
    }

    // 2) Causal multi-head attention (fp32)
    {
        cudaFuncSetAttribute(attn_kernel,
                             cudaFuncAttributeMaxDynamicSharedMemorySize,
                             kAttnSmemBytes);
        dim3 grid2(kSeq / 64, kBatch * 16);
        attn_kernel<<<grid2, 256, kAttnSmemBytes>>>(qkvp, attnp);
    }

    // 3) Output projection + bias (tensor cores)
    f2h_kernel<<<(kRows * kEmb) / 2048, 256>>>(attnp, at16, kRows * kEmb);
    {
        dim3 grid3(kEmb / 128, kRows / 128);
        gemm_mma_kernel<<<grid3, 256>>>(at16, wp16, b_proj, outp, kRows, kEmb, kEmb);
    }
}

// round 9
// speedup vs baseline: 10.9427x; 3.4191x over previous
#include <cuda_runtime.h>
#include <cuda_fp16.h>
#include <math_constants.h>
#include <cstdint>
#include <cstddef>

typedef unsigned int u32;

// ---------------------------------------------------------------------------
// Problem constants
// ---------------------------------------------------------------------------
constexpr int kBatch = 2;
constexpr int kSeq   = 2048;
constexpr int kEmb   = 1024;
constexpr int kHs    = 64;
constexpr int kRows  = kBatch * kSeq;   // 4096
constexpr int kQkvC  = 3 * kEmb;        // 3072

// Scratch (allocation-free rule: __device__ globals; zero-initialized)
__device__ __half g_x16[kRows * kEmb];
__device__ __half g_wqkv16[kEmb * kQkvC];
__device__ __half g_wproj16[kEmb * kEmb];
__device__ __half g_qkv16[kRows * kQkvC];
__device__ __half g_attn16[kRows * kEmb];
__device__ float  g_zero_bias[kQkvC];   // stays all-zero

// ---------------------------------------------------------------------------
// PTX helpers
// ---------------------------------------------------------------------------
static __device__ __forceinline__ void ldsm_x4(u32* r, u32 addr) {
    asm volatile(
        "ldmatrix.sync.aligned.m8n8.x4.shared.b16 { %0, %1, %2, %3 }, [ %4 ];\n"
        : "=r"(r[0]), "=r"(r[1]), "=r"(r[2]), "=r"(r[3])
        : "r"(addr));
}

static __device__ __forceinline__ void ldsm_x4_t(u32* r, u32 addr) {
    asm volatile(
        "ldmatrix.sync.aligned.m8n8.x4.trans.shared.b16 { %0, %1, %2, %3 }, [ %4 ];\n"
        : "=r"(r[0]), "=r"(r[1]), "=r"(r[2]), "=r"(r[3])
        : "r"(addr));
}

static __device__ __forceinline__ void hmma(float* acc, const u32* af, const u32* bf) {
    asm volatile(
        "mma.sync.aligned.m16n8k16.row.col.f32.f16.f16.f32 "
        "{ %0, %1, %2, %3 }, { %4, %5, %6, %7 }, { %8, %9 }, { %0, %1, %2, %3 };\n"
        : "+f"(acc[0]), "+f"(acc[1]), "+f"(acc[2]), "+f"(acc[3])
        : "r"(af[0]), "r"(af[1]), "r"(af[2]), "r"(af[3]),
          "r"(bf[0]), "r"(bf[1]));
}

static __device__ __forceinline__ u32 packh2(float x, float y) {
    __half2 h = __floats2half2_rn(x, y);
    return *(u32*)&h;
}

// ---------------------------------------------------------------------------
// fp32 -> fp16 conversion, 8 elems/thread
// ---------------------------------------------------------------------------
__global__ __launch_bounds__(256) void f2h_kernel(
    const float* __restrict__ src, __half* __restrict__ dst, int n)
{
    int i = (blockIdx.x * 256 + threadIdx.x) * 8;
    if (i >= n) return;
    float4 v0 = *(const float4*)(src + i);
    float4 v1 = *(const float4*)(src + i + 4);
    __half2 h[4];
    h[0] = __floats2half2_rn(v0.x, v0.y);
    h[1] = __floats2half2_rn(v0.z, v0.w);
    h[2] = __floats2half2_rn(v1.x, v1.y);
    h[3] = __floats2half2_rn(v1.z, v1.w);
    *(uint4*)(dst + i) = *(uint4*)h;
}

// ---------------------------------------------------------------------------
// Tensor-core GEMM: C[M,N] = A[M,K](fp16) @ B[K,N](fp16) + bias, fp32 accum.
// CTA tile 128x128, 8 warps (warp tile 32x64), K-step 32, double-buffered.
// write_half: 1 -> write fp16 to Cph; 0 -> write fp32 to Cp.
// ---------------------------------------------------------------------------
constexpr int kAStr = 56;
constexpr int kBStr = 136;

__global__ __launch_bounds__(256) void gemm_mma_kernel(
    const __half* __restrict__ Ap, const __half* __restrict__ Bp,
    const float* __restrict__ bias, float* __restrict__ Cp,
    __half* __restrict__ Cph, int write_half,
    int M, int N, int K)
{
    __shared__ __half As[2][128 * kAStr];
    __shared__ __half Bs[2][32 * kBStr];

    const int tid  = threadIdx.x;
    const int lane = tid & 31;
    const int wid  = tid >> 5;
    const int warp_m = wid & 3;
    const int warp_n = wid >> 2;
    const int m0 = blockIdx.y * 128;
    const int n0 = blockIdx.x * 128;

    const int a_r0 = tid >> 2;
    const int a_c  = (tid & 3) * 8;
    const int b_r0 = tid >> 4;
    const int b_c  = (tid & 15) * 8;

    float acc[2][8][4];
    for (int mt = 0; mt < 2; mt++) {
        for (int nt = 0; nt < 8; nt++) {
            acc[mt][nt][0] = 0.0f;
            acc[mt][nt][1] = 0.0f;
            acc[mt][nt][2] = 0.0f;
            acc[mt][nt][3] = 0.0f;
        }
    }

    uint4 ra0;
    uint4 ra1;
    uint4 rb0;
    uint4 rb1;

    ra0 = *(const uint4*)(Ap + (size_t)(m0 + a_r0) * K + a_c);
    ra1 = *(const uint4*)(Ap + (size_t)(m0 + a_r0 + 64) * K + a_c);
    rb0 = *(const uint4*)(Bp + (size_t)b_r0 * N + n0 + b_c);
    rb1 = *(const uint4*)(Bp + (size_t)(b_r0 + 16) * N + n0 + b_c);

    int buf = 0;
    *(uint4*)(&As[buf][a_r0 * kAStr + a_c]) = ra0;
    *(uint4*)(&As[buf][(a_r0 + 64) * kAStr + a_c]) = ra1;
    *(uint4*)(&Bs[buf][b_r0 * kBStr + b_c]) = rb0;
    *(uint4*)(&Bs[buf][(b_r0 + 16) * kBStr + b_c]) = rb1;
    __syncthreads();

    const int iters = K / 32;
    for (int it = 0; it < iters; it++) {
        if (it + 1 < iters) {
            int k0 = (it + 1) * 32;
            ra0 = *(const uint4*)(Ap + (size_t)(m0 + a_r0) * K + k0 + a_c);
            ra1 = *(const uint4*)(Ap + (size_t)(m0 + a_r0 + 64) * K + k0 + a_c);
            rb0 = *(const uint4*)(Bp + (size_t)(k0 + b_r0) * N + n0 + b_c);
            rb1 = *(const uint4*)(Bp + (size_t)(k0 + b_r0 + 16) * N + n0 + b_c);
        }

        u32 sA = (u32)__cvta_generic_to_shared(&As[buf][0]);
        u32 sB = (u32)__cvta_generic_to_shared(&Bs[buf][0]);
        #pragma unroll
        for (int ks = 0; ks < 2; ks++) {
            u32 afrag[2][4];
            #pragma unroll
            for (int mt = 0; mt < 2; mt++) {
                int arow = warp_m * 32 + mt * 16 + (lane & 15);
                int acol = ks * 16 + (lane >> 4) * 8;
                ldsm_x4(afrag[mt], sA + (u32)(arow * kAStr + acol) * 2u);
            }
            u32 bfrag[8][2];
            #pragma unroll
            for (int p = 0; p < 4; p++) {
                int krow = ks * 16 + (lane & 7) + ((lane >> 3) & 1) * 8;
                int ncol = warp_n * 64 + p * 16 + (lane >> 4) * 8;
                u32 rr[4];
                ldsm_x4_t(rr, sB + (u32)(krow * kBStr + ncol) * 2u);
                bfrag[2 * p][0] = rr[0];
                bfrag[2 * p][1] = rr[1];
                bfrag[2 * p + 1][0] = rr[2];
                bfrag[2 * p + 1][1] = rr[3];
            }
            #pragma unroll
            for (int mt = 0; mt < 2; mt++) {
                #pragma unroll
                for (int nt = 0; nt < 8; nt++) {
                    hmma(acc[mt][nt], afrag[mt], bfrag[nt]);
                }
            }
        }

        if (it + 1 < iters) {
            int nb = buf ^ 1;
            *(uint4*)(&As[nb][a_r0 * kAStr + a_c]) = ra0;
            *(uint4*)(&As[nb][(a_r0 + 64) * kAStr + a_c]) = ra1;
            *(uint4*)(&Bs[nb][b_r0 * kBStr + b_c]) = rb0;
            *(uint4*)(&Bs[nb][(b_r0 + 16) * kBStr + b_c]) = rb1;
            __syncthreads();
            buf = nb;
        }
    }

    #pragma unroll
    for (int mt = 0; mt < 2; mt++) {
        #pragma unroll
        for (int nt = 0; nt < 8; nt++) {
            int orow = m0 + warp_m * 32 + mt * 16 + (lane >> 2);
            int ocol = n0 + warp_n * 64 + nt * 8 + (lane & 3) * 2;
            float2 bb = *(const float2*)(bias + ocol);
            float x0 = acc[mt][nt][0] + bb.x;
            float y0 = acc[mt][nt][1] + bb.y;
            float x1 = acc[mt][nt][2] + bb.x;
            float y1 = acc[mt][nt][3] + bb.y;
            if (write_half != 0) {
                __half2 h0 = __floats2half2_rn(x0, y0);
                __half2 h1 = __floats2half2_rn(x1, y1);
                *(__half2*)(Cph + (size_t)orow * N + ocol) = h0;
                *(__half2*)(Cph + (size_t)(orow + 8) * N + ocol) = h1;
            } else {
                float2 v0;
                float2 v1;
                v0.x = x0; v0.y = y0;
                v1.x = x1; v1.y = y1;
                *(float2*)(Cp + (size_t)orow * N + ocol) = v0;
                *(float2*)(Cp + (size_t)(orow + 8) * N + ocol) = v1;
            }
        }
    }
}

// ---------------------------------------------------------------------------
// Tensor-core flash attention.
// Block: 64 query rows of one (b,h). 128 threads / 4 warps, warp = 16 rows.
// S = Q@K^T via mma (K stored [key][d] = col-major B, non-trans ldmatrix).
// Register-resident online softmax (quad shuffles). PV via mma (V trans ldm).
// Output fp16 in [b,t,h*hs] layout.
// ---------------------------------------------------------------------------
constexpr int kQPad = 72;  // halves; 8-row ldmatrix phases hit distinct banks

__global__ __launch_bounds__(128) void attn_mma_kernel(
    const __half* __restrict__ qkv, __half* __restrict__ outp)
{
    __shared__ __half Qs[64 * kQPad];
    __shared__ __half Ks[64 * kQPad];
    __shared__ __half Vs[64 * kQPad];

    const int tid  = threadIdx.x;
    const int lane = tid & 31;
    const int w    = tid >> 5;
    const int q0   = blockIdx.x * 64;
    const int bh   = blockIdx.y;
    const int bi   = bh >> 4;
    const int hi   = bh & 15;

    const __half* qb = qkv + (size_t)bi * kSeq * kQkvC + hi * kHs;
    const __half* kb = qb + kEmb;
    const __half* vb = qb + 2 * kEmb;

    // Load Q tile (64 rows x 64 halves)
    #pragma unroll
    for (int i = 0; i < 4; i++) {
        int idx = tid + i * 128;
        int row = idx >> 3;
        int cg  = (idx & 7) * 8;
        *(uint4*)(&Qs[row * kQPad + cg]) =
            *(const uint4*)(qb + (size_t)(q0 + row) * kQkvC + cg);
    }
    __syncthreads();

    u32 sQ = (u32)__cvta_generic_to_shared(&Qs[0]);
    u32 sK = (u32)__cvta_generic_to_shared(&Ks[0]);
    u32 sV = (u32)__cvta_generic_to_shared(&Vs[0]);

    // Q fragments: 4 k-steps of 16 over d=64
    u32 qf[4][4];
    #pragma unroll
    for (int ks = 0; ks < 4; ks++) {
        int row = w * 16 + (lane & 15);
        int col = ks * 16 + (lane >> 4) * 8;
        ldsm_x4(qf[ks], sQ + (u32)(row * kQPad + col) * 2u);
    }

    float o[8][4];
    #pragma unroll
    for (int nt = 0; nt < 8; nt++) {
        o[nt][0] = 0.0f; o[nt][1] = 0.0f; o[nt][2] = 0.0f; o[nt][3] = 0.0f;
    }
    float m0 = -1e30f;
    float m1 = -1e30f;
    float l0 = 0.0f;
    float l1 = 0.0f;

    const int r0loc = w * 16 + (lane >> 2);   // local row for acc slots 0,1
    const int r1loc = r0loc + 8;              // local row for acc slots 2,3

    for (int j0 = 0; j0 <= q0; j0 += 64) {
        __syncthreads();
        #pragma unroll
        for (int i = 0; i < 4; i++) {
            int idx = tid + i * 128;
            int row = idx >> 3;
            int cg  = (idx & 7) * 8;
            *(uint4*)(&Ks[row * kQPad + cg]) =
                *(const uint4*)(kb + (size_t)(j0 + row) * kQkvC + cg);
            *(uint4*)(&Vs[row * kQPad + cg]) =
                *(const uint4*)(vb + (size_t)(j0 + row) * kQkvC + cg);
        }
        __syncthreads();

        // S = Q @ K^T  (8 n-tiles of 8 keys)
        float s[8][4];
        #pragma unroll
        for (int nt = 0; nt < 8; nt++) {
            s[nt][0] = 0.0f; s[nt][1] = 0.0f; s[nt][2] = 0.0f; s[nt][3] = 0.0f;
        }
        #pragma unroll
        for (int ks = 0; ks < 4; ks++) {
            u32 kf[8][2];
            #pragma unroll
            for (int p = 0; p < 4; p++) {
                int nrow = p * 16 + (lane & 7) + ((lane >> 4) & 1) * 8;
                int kcol = ks * 16 + ((lane >> 3) & 1) * 8;
                u32 rr[4];
                ldsm_x4(rr, sK + (u32)(nrow * kQPad + kcol) * 2u);
                kf[2 * p][0] = rr[0];
                kf[2 * p][1] = rr[1];
                kf[2 * p + 1][0] = rr[2];
                kf[2 * p + 1][1] = rr[3];
            }
            #pragma unroll
            for (int nt = 0; nt < 8; nt++) {
                hmma(s[nt], qf[ks], kf[nt]);
            }
        }

        // scale + causal mask (diagonal tile only)
        const float scale = 0.125f;
        if (j0 == q0) {
            #pragma unroll
            for (int nt = 0; nt < 8; nt++) {
                int c0 = nt * 8 + (lane & 3) * 2;
                int c1 = c0 + 1;
                s[nt][0] = (c0 > r0loc) ? -1e30f : s[nt][0] * scale;
                s[nt][1] = (c1 > r0loc) ? -1e30f : s[nt][1] * scale;
                s[nt][2] = (c0 > r1loc) ? -1e30f : s[nt][2] * scale;
                s[nt][3] = (c1 > r1loc) ? -1e30f : s[nt][3] * scale;
            }
        } else {
            #pragma unroll
            for (int nt = 0; nt < 8; nt++) {
                s[nt][0] *= scale;
                s[nt][1] *= scale;
                s[nt][2] *= scale;
                s[nt][3] *= scale;
            }
        }

        // online softmax (register-resident; quad reduction over lanes ^1,^2)
        float mn0 = m0;
        float mn1 = m1;
        #pragma unroll
        for (int nt = 0; nt < 8; nt++) {
            mn0 = fmaxf(mn0, fmaxf(s[nt][0], s[nt][1]));
            mn1 = fmaxf(mn1, fmaxf(s[nt][2], s[nt][3]));
        }
        mn0 = fmaxf(mn0, __shfl_xor_sync(0xffffffffu, mn0, 1));
        mn0 = fmaxf(mn0, __shfl_xor_sync(0xffffffffu, mn0, 2));
        mn1 = fmaxf(mn1, __shfl_xor_sync(0xffffffffu, mn1, 1));
        mn1 = fmaxf(mn1, __shfl_xor_sync(0xffffffffu, mn1, 2));

        float sc0 = __expf(m0 - mn0);
        float sc1 = __expf(m1 - mn1);
        m0 = mn0;
        m1 = mn1;

        float rs0 = 0.0f;
        float rs1 = 0.0f;
        #pragma unroll
        for (int nt = 0; nt < 8; nt++) {
            float p0 = __expf(s[nt][0] - m0);
            float p1 = __expf(s[nt][1] - m0);
            float p2 = __expf(s[nt][2] - m1);
            float p3 = __expf(s[nt][3] - m1);
            s[nt][0] = p0; s[nt][1] = p1; s[nt][2] = p2; s[nt][3] = p3;
            rs0 += p0 + p1;
            rs1 += p2 + p3;
        }
        l0 = l0 * sc0 + rs0;
        l1 = l1 * sc1 + rs1;

        #pragma unroll
        for (int nt = 0; nt < 8; nt++) {
            o[nt][0] *= sc0;
            o[nt][1] *= sc0;
            o[nt][2] *= sc1;
            o[nt][3] *= sc1;
        }

        // O += P @ V   (4 key-chunks of 16; 8 d-tiles of 8)
        #pragma unroll
        for (int kc = 0; kc < 4; kc++) {
            u32 pa[4];
            pa[0] = packh2(s[2 * kc][0], s[2 * kc][1]);
            pa[1] = packh2(s[2 * kc][2], s[2 * kc][3]);
            pa[2] = packh2(s[2 * kc + 1][0], s[2 * kc + 1][1]);
            pa[3] = packh2(s[2 * kc + 1][2], s[2 * kc + 1][3]);
            u32 vf[8][2];
            #pragma unroll
            for (int p = 0; p < 4; p++) {
                int krow = kc * 16 + (lane & 7) + ((lane >> 3) & 1) * 8;
                int ncol = p * 16 + (lane >> 4) * 8;
                u32 rr[4];
                ldsm_x4_t(rr, sV + (u32)(krow * kQPad + ncol) * 2u);
                vf[2 * p][0] = rr[0];
                vf[2 * p][1] = rr[1];
                vf[2 * p + 1][0] = rr[2];
                vf[2 * p + 1][1] = rr[3];
            }
            #pragma unroll
            for (int nt = 0; nt < 8; nt++) {
                hmma(o[nt], pa, vf[nt]);
            }
        }
    }

    // final row-sum reduction + normalize + store fp16
    l0 += __shfl_xor_sync(0xffffffffu, l0, 1);
    l0 += __shfl_xor_sync(0xffffffffu, l0, 2);
    l1 += __shfl_xor_sync(0xffffffffu, l1, 1);
    l1 += __shfl_xor_sync(0xffffffffu, l1, 2);
    float inv0 = 1.0f / l0;
    float inv1 = 1.0f / l1;

    size_t row0 = (size_t)(bi * kSeq + q0 + r0loc) * kEmb + hi * kHs;
    size_t row1 = (size_t)(bi * kSeq + q0 + r1loc) * kEmb + hi * kHs;
    #pragma unroll
    for (int nt = 0; nt < 8; nt++) {
        int col = nt * 8 + (lane & 3) * 2;
        __half2 h0 = __floats2half2_rn(o[nt][0] * inv0, o[nt][1] * inv0);
        __half2 h1 = __floats2half2_rn(o[nt][2] * inv1, o[nt][3] * inv1);
        *(__half2*)(outp + row0 + col) = h0;
        *(__half2*)(outp + row1 + col) = h1;
    }
}

// ---------------------------------------------------------------------------
// Launch
// ---------------------------------------------------------------------------
extern "C" void kernel_launch(void* const* d_in, const int* in_sizes, int n_in,
                              void* d_out, int out_size)
{
    const float* x = (const float*)d_in[0];
    const float* w_qkv = (const float*)d_in[1];
    const float* w_proj = (const float*)d_in[2];
    const float* b_proj = (const float*)d_in[3];
    float* outp = (float*)d_out;

    float* zbias = 0;
    __half* x16 = 0;
    __half* wq16 = 0;
    __half* wp16 = 0;
    __half* qkv16 = 0;
    __half* at16 = 0;
    cudaGetSymbolAddress((void**)&zbias, g_zero_bias);
    cudaGetSymbolAddress((void**)&x16, g_x16);
    cudaGetSymbolAddress((void**)&wq16, g_wqkv16);
    cudaGetSymbolAddress((void**)&wp16, g_wproj16);
    cudaGetSymbolAddress((void**)&qkv16, g_qkv16);
    cudaGetSymbolAddress((void**)&at16, g_attn16);

    // fp32 -> fp16 conversions
    f2h_kernel<<<(kRows * kEmb) / 2048, 256>>>(x, x16, kRows * kEmb);
    f2h_kernel<<<(kEmb * kQkvC) / 2048, 256>>>(w_qkv, wq16, kEmb * kQkvC);
    f2h_kernel<<<(kEmb * kEmb) / 2048, 256>>>(w_proj, wp16, kEmb * kEmb);

    // 1) QKV projection (tensor cores) -> fp16 output
    {
        dim3 grid1(kQkvC / 128, kRows / 128);
        gemm_mma_kernel<<<grid1, 256>>>(x16, wq16, zbias, (float*)0, qkv16, 1,
                                        kRows, kQkvC, kEmb);
    }

    // 2) Causal multi-head attention (tensor cores) -> fp16 output
    {
        dim3 grid2(kSeq / 64, kBatch * 16);
        attn_mma_kernel<<<grid2, 128>>>(qkv16, at16);
    }

    // 3) Output projection + bias (tensor cores) -> fp32 output
    {
        dim3 grid3(kEmb / 128, kRows / 128);
        gemm_mma_kernel<<<grid3, 256>>>(at16, wp16, b_proj, outp, (__half*)0, 0,
                                        kRows, kEmb, kEmb);
    }
}

// round 10
// speedup vs baseline: 12.0813x; 1.1041x over previous
#include <cuda_runtime.h>
#include <cuda_fp16.h>
#include <math_constants.h>
#include <cstdint>
#include <cstddef>

typedef unsigned int u32;

// ---------------------------------------------------------------------------
// Problem constants
// ---------------------------------------------------------------------------
constexpr int kBatch = 2;
constexpr int kSeq   = 2048;
constexpr int kEmb   = 1024;
constexpr int kHs    = 64;
constexpr int kRows  = kBatch * kSeq;   // 4096
constexpr int kQkvC  = 3 * kEmb;        // 3072

// Scratch (allocation-free rule: __device__ globals; zero-initialized)
__device__ __half g_x16[kRows * kEmb];
__device__ __half g_wqkv16[kEmb * kQkvC];
__device__ __half g_wproj16[kEmb * kEmb];
__device__ __half g_qkv16[kRows * kQkvC];
__device__ __half g_attn16[kRows * kEmb];
__device__ float  g_zero_bias[kQkvC];   // stays all-zero

// ---------------------------------------------------------------------------
// PTX helpers
// ---------------------------------------------------------------------------
static __device__ __forceinline__ void ldsm_x4(u32* r, u32 addr) {
    asm volatile(
        "ldmatrix.sync.aligned.m8n8.x4.shared.b16 { %0, %1, %2, %3 }, [ %4 ];\n"
        : "=r"(r[0]), "=r"(r[1]), "=r"(r[2]), "=r"(r[3])
        : "r"(addr));
}

static __device__ __forceinline__ void ldsm_x4_t(u32* r, u32 addr) {
    asm volatile(
        "ldmatrix.sync.aligned.m8n8.x4.trans.shared.b16 { %0, %1, %2, %3 }, [ %4 ];\n"
        : "=r"(r[0]), "=r"(r[1]), "=r"(r[2]), "=r"(r[3])
        : "r"(addr));
}

static __device__ __forceinline__ void hmma(float* acc, const u32* af, const u32* bf) {
    asm volatile(
        "mma.sync.aligned.m16n8k16.row.col.f32.f16.f16.f32 "
        "{ %0, %1, %2, %3 }, { %4, %5, %6, %7 }, { %8, %9 }, { %0, %1, %2, %3 };\n"
        : "+f"(acc[0]), "+f"(acc[1]), "+f"(acc[2]), "+f"(acc[3])
        : "r"(af[0]), "r"(af[1]), "r"(af[2]), "r"(af[3]),
          "r"(bf[0]), "r"(bf[1]));
}

static __device__ __forceinline__ u32 packh2(float x, float y) {
    __half2 h = __floats2half2_rn(x, y);
    return *(u32*)&h;
}

static __device__ __forceinline__ void cp16(u32 dst, const __half* src) {
    asm volatile(
        "cp.async.cg.shared.global [ %0 ], [ %1 ], 16;\n"
        :: "r"(dst), "l"(__cvta_generic_to_global(src)));
}

static __device__ __forceinline__ void cp_commit() {
    asm volatile("cp.async.commit_group;\n");
}

static __device__ __forceinline__ void cp_wait0() {
    asm volatile("cp.async.wait_group 0;\n");
}

static __device__ __forceinline__ void cp_wait1() {
    asm volatile("cp.async.wait_group 1;\n");
}

static __device__ __forceinline__ void cp_wait2() {
    asm volatile("cp.async.wait_group 2;\n");
}

// ---------------------------------------------------------------------------
// fp32 -> fp16 conversion, 8 elems/thread
// ---------------------------------------------------------------------------
__global__ __launch_bounds__(256) void f2h_kernel(
    const float* __restrict__ src, __half* __restrict__ dst, int n)
{
    int i = (blockIdx.x * 256 + threadIdx.x) * 8;
    if (i >= n) return;
    float4 v0 = *(const float4*)(src + i);
    float4 v1 = *(const float4*)(src + i + 4);
    __half2 h[4];
    h[0] = __floats2half2_rn(v0.x, v0.y);
    h[1] = __floats2half2_rn(v0.z, v0.w);
    h[2] = __floats2half2_rn(v1.x, v1.y);
    h[3] = __floats2half2_rn(v1.z, v1.w);
    *(uint4*)(dst + i) = *(uint4*)h;
}

// ---------------------------------------------------------------------------
// Tensor-core GEMM with cp.async 4-stage pipeline.
// C[M,N] = A[M,K](fp16) @ B[K,N](fp16) + bias, fp32 accum.
// CTA tile 128x128, 8 warps (warp tile 32x64), K-step 32.
// ---------------------------------------------------------------------------
constexpr int kAS = 40;                 // A smem row stride (halves), 128x32 tile
constexpr int kBS = 136;                // B smem row stride (halves), 32x128 tile
constexpr int kAStage = 128 * kAS;      // 5120 halves
constexpr int kBStage = 32 * kBS;       // 4352 halves
constexpr int kGemmSmem = 4 * (kAStage + kBStage) * 2;  // 75776 bytes

static __device__ __forceinline__ void gemm_prefetch(
    const __half* Ap, const __half* Bp, __half* Asm, __half* Bsm,
    int stage, int k0, int m0, int n0, int K, int N, int tid)
{
    u32 sa = (u32)__cvta_generic_to_shared(Asm + stage * kAStage);
    u32 sb = (u32)__cvta_generic_to_shared(Bsm + stage * kBStage);
    #pragma unroll
    for (int i = 0; i < 2; i++) {
        int c = tid + i * 256;
        int ar = c >> 2;
        int ac = (c & 3) * 8;
        cp16(sa + (u32)(ar * kAS + ac) * 2u,
             Ap + (size_t)(m0 + ar) * K + k0 + ac);
        int br = c >> 4;
        int bc = (c & 15) * 8;
        cp16(sb + (u32)(br * kBS + bc) * 2u,
             Bp + (size_t)(k0 + br) * N + n0 + bc);
    }
}

__global__ __launch_bounds__(256) void gemm_mma_kernel(
    const __half* __restrict__ Ap, const __half* __restrict__ Bp,
    const float* __restrict__ bias, float* __restrict__ Cp,
    __half* __restrict__ Cph, int write_half,
    int M, int N, int K)
{
    extern __shared__ __half dsm[];
    __half* Asm = dsm;
    __half* Bsm = dsm + 4 * kAStage;

    const int tid  = threadIdx.x;
    const int lane = tid & 31;
    const int wid  = tid >> 5;
    const int warp_m = wid & 3;
    const int warp_n = wid >> 2;
    const int m0 = blockIdx.y * 128;
    const int n0 = blockIdx.x * 128;

    float acc[2][8][4];
    for (int mt = 0; mt < 2; mt++) {
        for (int nt = 0; nt < 8; nt++) {
            acc[mt][nt][0] = 0.0f;
            acc[mt][nt][1] = 0.0f;
            acc[mt][nt][2] = 0.0f;
            acc[mt][nt][3] = 0.0f;
        }
    }

    const int iters = K / 32;

    // prologue: fill up to 3 stages
    for (int s = 0; s < 3; s++) {
        if (s < iters) {
            gemm_prefetch(Ap, Bp, Asm, Bsm, s, s * 32, m0, n0, K, N, tid);
        }
        cp_commit();
    }

    for (int it = 0; it < iters; it++) {
        int rem = iters - it;
        if (rem >= 3) {
            cp_wait2();
        } else if (rem == 2) {
            cp_wait1();
        } else {
            cp_wait0();
        }
        __syncthreads();

        u32 sA = (u32)__cvta_generic_to_shared(Asm + (it & 3) * kAStage);
        u32 sB = (u32)__cvta_generic_to_shared(Bsm + (it & 3) * kBStage);
        #pragma unroll
        for (int ks = 0; ks < 2; ks++) {
            u32 afrag[2][4];
            #pragma unroll
            for (int mt = 0; mt < 2; mt++) {
                int arow = warp_m * 32 + mt * 16 + (lane & 15);
                int acol = ks * 16 + (lane >> 4) * 8;
                ldsm_x4(afrag[mt], sA + (u32)(arow * kAS + acol) * 2u);
            }
            u32 bfrag[8][2];
            #pragma unroll
            for (int p = 0; p < 4; p++) {
                int krow = ks * 16 + (lane & 7) + ((lane >> 3) & 1) * 8;
                int ncol = warp_n * 64 + p * 16 + (lane >> 4) * 8;
                u32 rr[4];
                ldsm_x4_t(rr, sB + (u32)(krow * kBS + ncol) * 2u);
                bfrag[2 * p][0] = rr[0];
                bfrag[2 * p][1] = rr[1];
                bfrag[2 * p + 1][0] = rr[2];
                bfrag[2 * p + 1][1] = rr[3];
            }
            #pragma unroll
            for (int mt = 0; mt < 2; mt++) {
                #pragma unroll
                for (int nt = 0; nt < 8; nt++) {
                    hmma(acc[mt][nt], afrag[mt], bfrag[nt]);
                }
            }
        }

        if (it + 3 < iters) {
            gemm_prefetch(Ap, Bp, Asm, Bsm, (it + 3) & 3, (it + 3) * 32,
                          m0, n0, K, N, tid);
        }
        cp_commit();
    }

    #pragma unroll
    for (int mt = 0; mt < 2; mt++) {
        #pragma unroll
        for (int nt = 0; nt < 8; nt++) {
            int orow = m0 + warp_m * 32 + mt * 16 + (lane >> 2);
            int ocol = n0 + warp_n * 64 + nt * 8 + (lane & 3) * 2;
            float2 bb = *(const float2*)(bias + ocol);
            float x0 = acc[mt][nt][0] + bb.x;
            float y0 = acc[mt][nt][1] + bb.y;
            float x1 = acc[mt][nt][2] + bb.x;
            float y1 = acc[mt][nt][3] + bb.y;
            if (write_half != 0) {
                __half2 h0 = __floats2half2_rn(x0, y0);
                __half2 h1 = __floats2half2_rn(x1, y1);
                *(__half2*)(Cph + (size_t)orow * N + ocol) = h0;
                *(__half2*)(Cph + (size_t)(orow + 8) * N + ocol) = h1;
            } else {
                float2 v0;
                float2 v1;
                v0.x = x0; v0.y = y0;
                v1.x = x1; v1.y = y1;
                *(float2*)(Cp + (size_t)orow * N + ocol) = v0;
                *(float2*)(Cp + (size_t)(orow + 8) * N + ocol) = v1;
            }
        }
    }
}

// ---------------------------------------------------------------------------
// Tensor-core flash attention with cp.async double-buffered K/V.
// Block: 64 query rows of one (b,h). 128 threads / 4 warps, warp = 16 rows.
// ---------------------------------------------------------------------------
constexpr int kQPad = 72;               // halves
constexpr int kKVStage = 64 * kQPad;    // 4608 halves per tile

static __device__ __forceinline__ void attn_prefetch(
    const __half* kb, const __half* vb, __half* Ks, __half* Vs,
    int buf, int j0, int tid)
{
    u32 sk = (u32)__cvta_generic_to_shared(Ks + buf * kKVStage);
    u32 sv = (u32)__cvta_generic_to_shared(Vs + buf * kKVStage);
    #pragma unroll
    for (int i = 0; i < 4; i++) {
        int c = tid + i * 128;
        int row = c >> 3;
        int col = (c & 7) * 8;
        cp16(sk + (u32)(row * kQPad + col) * 2u,
             kb + (size_t)(j0 + row) * kQkvC + col);
        cp16(sv + (u32)(row * kQPad + col) * 2u,
             vb + (size_t)(j0 + row) * kQkvC + col);
    }
}

__global__ __launch_bounds__(128) void attn_mma_kernel(
    const __half* __restrict__ qkv, __half* __restrict__ outp)
{
    __shared__ __half Qs[64 * kQPad];
    __shared__ __half Ks[2 * kKVStage];
    __shared__ __half Vs[2 * kKVStage];

    const int tid  = threadIdx.x;
    const int lane = tid & 31;
    const int w    = tid >> 5;
    const int q0   = blockIdx.x * 64;
    const int bh   = blockIdx.y;
    const int bi   = bh >> 4;
    const int hi   = bh & 15;

    const __half* qb = qkv + (size_t)bi * kSeq * kQkvC + hi * kHs;
    const __half* kb = qb + kEmb;
    const __half* vb = qb + 2 * kEmb;

    // prefetch K/V tile 0 while loading Q
    attn_prefetch(kb, vb, Ks, Vs, 0, 0, tid);
    cp_commit();

    // Load Q tile (64 rows x 64 halves)
    #pragma unroll
    for (int i = 0; i < 4; i++) {
        int idx = tid + i * 128;
        int row = idx >> 3;
        int cg  = (idx & 7) * 8;
        *(uint4*)(&Qs[row * kQPad + cg]) =
            *(const uint4*)(qb + (size_t)(q0 + row) * kQkvC + cg);
    }
    __syncthreads();

    u32 sQ = (u32)__cvta_generic_to_shared(&Qs[0]);

    u32 qf[4][4];
    #pragma unroll
    for (int ks = 0; ks < 4; ks++) {
        int row = w * 16 + (lane & 15);
        int col = ks * 16 + (lane >> 4) * 8;
        ldsm_x4(qf[ks], sQ + (u32)(row * kQPad + col) * 2u);
    }

    float o[8][4];
    #pragma unroll
    for (int nt = 0; nt < 8; nt++) {
        o[nt][0] = 0.0f; o[nt][1] = 0.0f; o[nt][2] = 0.0f; o[nt][3] = 0.0f;
    }
    float m0 = -1e30f;
    float m1 = -1e30f;
    float l0 = 0.0f;
    float l1 = 0.0f;

    const int r0loc = w * 16 + (lane >> 2);
    const int r1loc = r0loc + 8;

    const int ntiles = q0 / 64 + 1;
    int buf = 0;

    for (int t = 0; t < ntiles; t++) {
        if (t + 1 < ntiles) {
            attn_prefetch(kb, vb, Ks, Vs, buf ^ 1, (t + 1) * 64, tid);
            cp_commit();
            cp_wait1();
        } else {
            cp_wait0();
        }
        __syncthreads();

        u32 sK = (u32)__cvta_generic_to_shared(Ks + buf * kKVStage);
        u32 sV = (u32)__cvta_generic_to_shared(Vs + buf * kKVStage);

        // S = Q @ K^T
        float s[8][4];
        #pragma unroll
        for (int nt = 0; nt < 8; nt++) {
            s[nt][0] = 0.0f; s[nt][1] = 0.0f; s[nt][2] = 0.0f; s[nt][3] = 0.0f;
        }
        #pragma unroll
        for (int ks = 0; ks < 4; ks++) {
            u32 kf[8][2];
            #pragma unroll
            for (int p = 0; p < 4; p++) {
                int nrow = p * 16 + (lane & 7) + ((lane >> 4) & 1) * 8;
                int kcol = ks * 16 + ((lane >> 3) & 1) * 8;
                u32 rr[4];
                ldsm_x4(rr, sK + (u32)(nrow * kQPad + kcol) * 2u);
                kf[2 * p][0] = rr[0];
                kf[2 * p][1] = rr[1];
                kf[2 * p + 1][0] = rr[2];
                kf[2 * p + 1][1] = rr[3];
            }
            #pragma unroll
            for (int nt = 0; nt < 8; nt++) {
                hmma(s[nt], qf[ks], kf[nt]);
            }
        }

        const float scale = 0.125f;
        if (t == ntiles - 1) {
            #pragma unroll
            for (int nt = 0; nt < 8; nt++) {
                int c0 = nt * 8 + (lane & 3) * 2;
                int c1 = c0 + 1;
                s[nt][0] = (c0 > r0loc) ? -1e30f : s[nt][0] * scale;
                s[nt][1] = (c1 > r0loc) ? -1e30f : s[nt][1] * scale;
                s[nt][2] = (c0 > r1loc) ? -1e30f : s[nt][2] * scale;
                s[nt][3] = (c1 > r1loc) ? -1e30f : s[nt][3] * scale;
            }
        } else {
            #pragma unroll
            for (int nt = 0; nt < 8; nt++) {
                s[nt][0] *= scale;
                s[nt][1] *= scale;
                s[nt][2] *= scale;
                s[nt][3] *= scale;
            }
        }

        // online softmax (register-resident)
        float mn0 = m0;
        float mn1 = m1;
        #pragma unroll
        for (int nt = 0; nt < 8; nt++) {
            mn0 = fmaxf(mn0, fmaxf(s[nt][0], s[nt][1]));
            mn1 = fmaxf(mn1, fmaxf(s[nt][2], s[nt][3]));
        }
        mn0 = fmaxf(mn0, __shfl_xor_sync(0xffffffffu, mn0, 1));
        mn0 = fmaxf(mn0, __shfl_xor_sync(0xffffffffu, mn0, 2));
        mn1 = fmaxf(mn1, __shfl_xor_sync(0xffffffffu, mn1, 1));
        mn1 = fmaxf(mn1, __shfl_xor_sync(0xffffffffu, mn1, 2));

        float sc0 = __expf(m0 - mn0);
        float sc1 = __expf(m1 - mn1);
        m0 = mn0;
        m1 = mn1;

        float rs0 = 0.0f;
        float rs1 = 0.0f;
        #pragma unroll
        for (int nt = 0; nt < 8; nt++) {
            float p0 = __expf(s[nt][0] - m0);
            float p1 = __expf(s[nt][1] - m0);
            float p2 = __expf(s[nt][2] - m1);
            float p3 = __expf(s[nt][3] - m1);
            s[nt][0] = p0; s[nt][1] = p1; s[nt][2] = p2; s[nt][3] = p3;
            rs0 += p0 + p1;
            rs1 += p2 + p3;
        }
        l0 = l0 * sc0 + rs0;
        l1 = l1 * sc1 + rs1;

        #pragma unroll
        for (int nt = 0; nt < 8; nt++) {
            o[nt][0] *= sc0;
            o[nt][1] *= sc0;
            o[nt][2] *= sc1;
            o[nt][3] *= sc1;
        }

        // O += P @ V
        #pragma unroll
        for (int kc = 0; kc < 4; kc++) {
            u32 pa[4];
            pa[0] = packh2(s[2 * kc][0], s[2 * kc][1]);
            pa[1] = packh2(s[2 * kc][2], s[2 * kc][3]);
            pa[2] = packh2(s[2 * kc + 1][0], s[2 * kc + 1][1]);
            pa[3] = packh2(s[2 * kc + 1][2], s[2 * kc + 1][3]);
            u32 vf[8][2];
            #pragma unroll
            for (int p = 0; p < 4; p++) {
                int krow = kc * 16 + (lane & 7) + ((lane >> 3) & 1) * 8;
                int ncol = p * 16 + (lane >> 4) * 8;
                u32 rr[4];
                ldsm_x4_t(rr, sV + (u32)(krow * kQPad + ncol) * 2u);
                vf[2 * p][0] = rr[0];
                vf[2 * p][1] = rr[1];
                vf[2 * p + 1][0] = rr[2];
                vf[2 * p + 1][1] = rr[3];
            }
            #pragma unroll
            for (int nt = 0; nt < 8; nt++) {
                hmma(o[nt], pa, vf[nt]);
            }
        }

        __syncthreads();
        buf ^= 1;
    }

    l0 += __shfl_xor_sync(0xffffffffu, l0, 1);
    l0 += __shfl_xor_sync(0xffffffffu, l0, 2);
    l1 += __shfl_xor_sync(0xffffffffu, l1, 1);
    l1 += __shfl_xor_sync(0xffffffffu, l1, 2);
    float inv0 = 1.0f / l0;
    float inv1 = 1.0f / l1;

    size_t row0 = (size_t)(bi * kSeq + q0 + r0loc) * kEmb + hi * kHs;
    size_t row1 = (size_t)(bi * kSeq + q0 + r1loc) * kEmb + hi * kHs;
    #pragma unroll
    for (int nt = 0; nt < 8; nt++) {
        int col = nt * 8 + (lane & 3) * 2;
        __half2 h0 = __floats2half2_rn(o[nt][0] * inv0, o[nt][1] * inv0);
        __half2 h1 = __floats2half2_rn(o[nt][2] * inv1, o[nt][3] * inv1);
        *(__half2*)(outp + row0 + col) = h0;
        *(__half2*)(outp + row1 + col) = h1;
    }
}

// ---------------------------------------------------------------------------
// Launch
// ---------------------------------------------------------------------------
extern "C" void kernel_launch(void* const* d_in, const int* in_sizes, int n_in,
                              void* d_out, int out_size)
{
    const float* x = (const float*)d_in[0];
    const float* w_qkv = (const float*)d_in[1];
    const float* w_proj = (const float*)d_in[2];
    const float* b_proj = (const float*)d_in[3];
    float* outp = (float*)d_out;

    float* zbias = 0;
    __half* x16 = 0;
    __half* wq16 = 0;
    __half* wp16 = 0;
    __half* qkv16 = 0;
    __half* at16 = 0;
    cudaGetSymbolAddress((void**)&zbias, g_zero_bias);
    cudaGetSymbolAddress((void**)&x16, g_x16);
    cudaGetSymbolAddress((void**)&wq16, g_wqkv16);
    cudaGetSymbolAddress((void**)&wp16, g_wproj16);
    cudaGetSymbolAddress((void**)&qkv16, g_qkv16);
    cudaGetSymbolAddress((void**)&at16, g_attn16);

    cudaFuncSetAttribute(gemm_mma_kernel,
                         cudaFuncAttributeMaxDynamicSharedMemorySize,
                         kGemmSmem);

    // fp32 -> fp16 conversions
    f2h_kernel<<<(kRows * kEmb) / 2048, 256>>>(x, x16, kRows * kEmb);
    f2h_kernel<<<(kEmb * kQkvC) / 2048, 256>>>(w_qkv, wq16, kEmb * kQkvC);
    f2h_kernel<<<(kEmb * kEmb) / 2048, 256>>>(w_proj, wp16, kEmb * kEmb);

    // 1) QKV projection (tensor cores) -> fp16
    {
        dim3 grid1(kQkvC / 128, kRows / 128);
        gemm_mma_kernel<<<grid1, 256, kGemmSmem>>>(
            x16, wq16, zbias, (float*)0, qkv16, 1, kRows, kQkvC, kEmb);
    }

    // 2) Causal multi-head attention (tensor cores) -> fp16
    {
        dim3 grid2(kSeq / 64, kBatch * 16);
        attn_mma_kernel<<<grid2, 128>>>(qkv16, at16);
    }

    // 3) Output projection + bias (tensor cores) -> fp32
    {
        dim3 grid3(kEmb / 128, kRows / 128);
        gemm_mma_kernel<<<grid3, 256, kGemmSmem>>>(
            at16, wp16, b_proj, outp, (__half*)0, 0, kRows, kEmb, kEmb);
    }
}